// round 2
// baseline (speedup 1.0000x reference)
#include <cuda_runtime.h>
#include <math.h>

// Problem constants (match reference)
#define BATCH   16384
#define CTX     8
#define NEGS    5
#define DIM     128
#define ROWF4   (DIM / 4)          // 32 float4 per embedding row
#define WPB     8                  // warps per block
#define TPB     (WPB * 32)
#define NBLOCKS (BATCH / WPB)      // 2048

// Per-block partial sums: [block][6] -> [0]=s_pos, [1..5]=s_neg[n]
__device__ float g_part[NBLOCKS][6];

__global__ __launch_bounds__(TPB) void cbow_partial_kernel(
    const int* __restrict__ pos_u,   // [B, C]
    const int* __restrict__ pos_w,   // [B]
    const int* __restrict__ neg_w,   // [B, N]
    const float4* __restrict__ Wv)   // [VOCAB, 32] as float4
{
    const int lane = threadIdx.x & 31;
    const int wid  = threadIdx.x >> 5;
    const int b    = blockIdx.x * WPB + wid;   // one batch per warp

    // Lanes 0..7: context indices; lane 8: positive; lanes 9..13: negatives.
    int idx = 0;
    if (lane < CTX)                 idx = pos_u[b * CTX + lane];
    else if (lane == CTX)           idx = pos_w[b];
    else if (lane < CTX + 1 + NEGS) idx = neg_w[b * NEGS + (lane - CTX - 1)];

    // Context sum: 8 independent coalesced row loads (MLP=8).
    float4 us = make_float4(0.f, 0.f, 0.f, 0.f);
#pragma unroll
    for (int c = 0; c < CTX; c++) {
        int r = __shfl_sync(0xffffffffu, idx, c);
        float4 v = Wv[(size_t)r * ROWF4 + lane];
        us.x += v.x; us.y += v.y; us.z += v.z; us.w += v.w;
    }

    // 6 target rows: dot against Usum.
    float p[6];
#pragma unroll
    for (int t = 0; t < 6; t++) {
        int r = __shfl_sync(0xffffffffu, idx, CTX + t);
        float4 v = Wv[(size_t)r * ROWF4 + lane];
        p[t] = us.x * v.x + us.y * v.y + us.z * v.z + us.w * v.w;
    }

    // Warp reduction of the 6 partials.
#pragma unroll
    for (int t = 0; t < 6; t++) {
        float v = p[t];
#pragma unroll
        for (int o = 16; o > 0; o >>= 1)
            v += __shfl_xor_sync(0xffffffffu, v, o);
        p[t] = v;
    }

    __shared__ float smem[6][WPB];
    if (lane == 0) {
#pragma unroll
        for (int t = 0; t < 6; t++) smem[t][wid] = p[t];
    }
    __syncthreads();

    // One deterministic store per block per accumulator (no atomics).
    if (threadIdx.x < 6) {
        float s = 0.0f;
#pragma unroll
        for (int i = 0; i < WPB; i++) s += smem[threadIdx.x][i];
        g_part[blockIdx.x][threadIdx.x] = s;
    }
}

__device__ __forceinline__ float log_sigmoid(float x) {
    // numerically stable log(sigmoid(x))
    return (x >= 0.0f) ? -log1pf(expf(-x)) : (x - log1pf(expf(x)));
}

__global__ __launch_bounds__(256) void finalize_kernel(float* __restrict__ out) {
    // Reduce 2048 x 6 partials with one block of 256 threads.
    __shared__ float acc[6][256];
    const int t = threadIdx.x;
    float s[6];
#pragma unroll
    for (int k = 0; k < 6; k++) s[k] = 0.0f;
    for (int i = t; i < NBLOCKS; i += 256) {
#pragma unroll
        for (int k = 0; k < 6; k++) s[k] += g_part[i][k];
    }
#pragma unroll
    for (int k = 0; k < 6; k++) acc[k][t] = s[k];
    __syncthreads();
    for (int stride = 128; stride > 0; stride >>= 1) {
        if (t < stride) {
#pragma unroll
            for (int k = 0; k < 6; k++) acc[k][t] += acc[k][t + stride];
        }
        __syncthreads();
    }
    if (t == 0) {
        float loss = -log_sigmoid(acc[0][0]);          // loss1
#pragma unroll
        for (int n = 0; n < NEGS; n++)
            loss -= log_sigmoid(-acc[1 + n][0]);       // - loss2
        out[0] = loss;
    }
}

extern "C" void kernel_launch(void* const* d_in, const int* in_sizes, int n_in,
                              void* d_out, int out_size) {
    const int*    pos_u = (const int*)d_in[0];
    const int*    pos_w = (const int*)d_in[1];
    const int*    neg_w = (const int*)d_in[2];
    const float4* Wv    = (const float4*)d_in[3];
    float*        out   = (float*)d_out;

    (void)in_sizes; (void)n_in; (void)out_size;

    cbow_partial_kernel<<<NBLOCKS, TPB>>>(pos_u, pos_w, neg_w, Wv);
    finalize_kernel<<<1, 256>>>(out);
}